// round 1
// baseline (speedup 1.0000x reference)
#include <cuda_runtime.h>
#include <math.h>

// params: R[9] (row-major, p_j = sum_i (v_i - t_i) * R[i*3+j]), t[3], inv_scale
__device__ float g_params[13];
#define NB_MAX 256
__device__ float g_partials[NB_MAX];

__global__ void setup_kernel(const float* __restrict__ state,
                             const float* __restrict__ scale) {
    if (threadIdx.x == 0) {
        float tx = state[0], ty = state[1], tz = state[2];
        float ox = state[3], oy = state[4], oz = state[5];
        float sx = sinf(ox), cx = cosf(ox);
        float sy = sinf(oy), cy = cosf(oy);
        float sz = sinf(oz), cz = cosf(oz);
        // R = Rz @ Ry @ Rx
        g_params[0] = cz * cy;
        g_params[1] = cz * sy * sx - sz * cx;
        g_params[2] = cz * sy * cx + sz * sx;
        g_params[3] = sz * cy;
        g_params[4] = sz * sy * sx + cz * cx;
        g_params[5] = sz * sy * cx - cz * sx;
        g_params[6] = -sy;
        g_params[7] = cy * sx;
        g_params[8] = cy * cx;
        g_params[9]  = tx;
        g_params[10] = ty;
        g_params[11] = tz;
        g_params[12] = 1.0f / scale[0];
    }
}

// 128 threads/CTA, full model set staged in dynamic SMEM as float4(x,y,z,|g|^2).
__global__ __launch_bounds__(128, 1)
void cd_kernel(const float* __restrict__ vis,
               const float* __restrict__ tac,
               const float* __restrict__ model,
               int nv, int nt, int nm,
               float wv, float wt) {
    extern __shared__ float4 s_model[];

    // Stage model points into shared, precomputing |g|^2.
    for (int j = threadIdx.x; j < nm; j += blockDim.x) {
        float gx = model[3 * j + 0];
        float gy = model[3 * j + 1];
        float gz = model[3 * j + 2];
        s_model[j] = make_float4(gx, gy, gz, gx * gx + gy * gy + gz * gz);
    }

    // Load transform params (L1-cached broadcast).
    float R00 = g_params[0], R01 = g_params[1], R02 = g_params[2];
    float R10 = g_params[3], R11 = g_params[4], R12 = g_params[5];
    float R20 = g_params[6], R21 = g_params[7], R22 = g_params[8];
    float t0 = g_params[9], t1 = g_params[10], t2 = g_params[11];
    float inv_s = g_params[12];

    __syncthreads();

    int i = blockIdx.x * blockDim.x + threadIdx.x;
    int ntot = nv + nt;
    bool active = (i < ntot);

    float px = 0.f, py = 0.f, pz = 0.f, w = 0.f;
    if (active) {
        const float* src;
        int idx;
        if (i < nv) { src = vis; idx = i;      w = wv; }
        else        { src = tac; idx = i - nv; w = wt; }
        float vx = src[3 * idx + 0] - t0;
        float vy = src[3 * idx + 1] - t1;
        float vz = src[3 * idx + 2] - t2;
        // row-vector times R, then / scale
        px = (vx * R00 + vy * R10 + vz * R20) * inv_s;
        py = (vx * R01 + vy * R11 + vz * R21) * inv_s;
        pz = (vx * R02 + vy * R12 + vz * R22) * inv_s;
    }

    float a  = px * px + py * py + pz * pz;
    float qx = -2.0f * px, qy = -2.0f * py, qz = -2.0f * pz;

    // min over model points of (b - 2 p.g); 4 independent accumulators for ILP.
    float m0 = 3.402823466e+38f, m1 = m0, m2 = m0, m3 = m0;
    int j = 0;
    int nm4 = nm & ~3;
    #pragma unroll 4
    for (; j < nm4; j += 4) {
        float4 g0 = s_model[j + 0];
        float4 g1 = s_model[j + 1];
        float4 g2 = s_model[j + 2];
        float4 g3 = s_model[j + 3];
        float d0 = fmaf(qx, g0.x, fmaf(qy, g0.y, fmaf(qz, g0.z, g0.w)));
        float d1 = fmaf(qx, g1.x, fmaf(qy, g1.y, fmaf(qz, g1.z, g1.w)));
        float d2 = fmaf(qx, g2.x, fmaf(qy, g2.y, fmaf(qz, g2.z, g2.w)));
        float d3 = fmaf(qx, g3.x, fmaf(qy, g3.y, fmaf(qz, g3.z, g3.w)));
        m0 = fminf(m0, d0);
        m1 = fminf(m1, d1);
        m2 = fminf(m2, d2);
        m3 = fminf(m3, d3);
    }
    for (; j < nm; j++) {
        float4 g0 = s_model[j];
        float d0 = fmaf(qx, g0.x, fmaf(qy, g0.y, fmaf(qz, g0.z, g0.w)));
        m0 = fminf(m0, d0);
    }
    float m = fminf(fminf(m0, m1), fminf(m2, m3));

    float val = active ? (a + m) * w : 0.0f;

    // Block reduction: warp shuffle + smem
    #pragma unroll
    for (int o = 16; o > 0; o >>= 1)
        val += __shfl_down_sync(0xffffffffu, val, o);
    __shared__ float s_red[4];
    int lane = threadIdx.x & 31;
    int wid  = threadIdx.x >> 5;
    if (lane == 0) s_red[wid] = val;
    __syncthreads();
    if (threadIdx.x == 0)
        g_partials[blockIdx.x] = s_red[0] + s_red[1] + s_red[2] + s_red[3];
}

// Deterministic fixed-order final sum.
__global__ void final_kernel(float* __restrict__ out, int nb) {
    if (threadIdx.x == 0 && blockIdx.x == 0) {
        float s = 0.0f;
        for (int b = 0; b < nb; b++) s += g_partials[b];
        out[0] = s;
    }
}

extern "C" void kernel_launch(void* const* d_in, const int* in_sizes, int n_in,
                              void* d_out, int out_size) {
    const float* vis   = (const float*)d_in[0];  // visual_points  (16384,3)
    const float* tac   = (const float*)d_in[1];  // tactile_points (2048,3)
    const float* model = (const float*)d_in[2];  // model_points   (8192,3)
    const float* scale = (const float*)d_in[3];  // scalar
    const float* state = (const float*)d_in[4];  // (6,)
    float* out = (float*)d_out;

    int nv = in_sizes[0] / 3;
    int nt = in_sizes[1] / 3;
    int nm = in_sizes[2] / 3;

    int ntot = nv + nt;
    int threads = 128;
    int nb = (ntot + threads - 1) / threads;   // 144 for default shapes
    if (nb > NB_MAX) nb = NB_MAX;              // safety (shapes are fixed)

    size_t smem = (size_t)nm * sizeof(float4); // 131072 B for nm=8192
    cudaFuncSetAttribute(cd_kernel, cudaFuncAttributeMaxDynamicSharedMemorySize,
                         (int)smem);

    float wv = 1.0f / (float)nv;
    float wt = 0.1f / (float)nt;

    setup_kernel<<<1, 32>>>(state, scale);
    cd_kernel<<<nb, threads, smem>>>(vis, tac, model, nv, nt, nm, wv, wt);
    final_kernel<<<1, 32>>>(out, nb);
}

// round 2
// speedup vs baseline: 1.4101x; 1.4101x over previous
#include <cuda_runtime.h>
#include <math.h>
#include <cstdint>
#include <float.h>

#define NB_MAX 256
__device__ float g_partials[NB_MAX];

// ---------------------------------------------------------------------------
// Main kernel: 512 threads/CTA. Each CTA owns 128 pred points; each point is
// processed by 4 lanes (sub = tid>>7), each covering 1/4 of the model set.
// Model set staged in dynamic SMEM pair-interleaved:
//   pair p: [x0,x1,y0,y1, z0,z1,w0,w1]  (w = |g|^2), 32 bytes/pair.
// Inner loop per pair: 2x ld.shared.v2.u64 + 3x fma.rn.f32x2 + 2x FMNMX.
// ---------------------------------------------------------------------------
__global__ __launch_bounds__(512, 1)
void cd_kernel(const float* __restrict__ vis,
               const float* __restrict__ tac,
               const float* __restrict__ model,
               const float* __restrict__ scale,
               const float* __restrict__ state,
               int nv, int nt, int nm,
               float wv, float wt) {
    extern __shared__ float s_model[];          // nm_pairs * 8 floats
    __shared__ float s_par[13];                 // R[9], t[3], inv_scale
    __shared__ float s_min[4 * 128];
    __shared__ float s_red[4];

    const int tid = threadIdx.x;
    const int nm_pairs = (nm + 1) >> 1;

    // ---- stage model points (pair-interleaved, with |g|^2) ----
    for (int j = tid; j < nm; j += blockDim.x) {
        float gx = model[3 * j + 0];
        float gy = model[3 * j + 1];
        float gz = model[3 * j + 2];
        int p = j >> 1, o = j & 1;
        s_model[p * 8 + 0 + o] = gx;
        s_model[p * 8 + 2 + o] = gy;
        s_model[p * 8 + 4 + o] = gz;
        s_model[p * 8 + 6 + o] = fmaf(gx, gx, fmaf(gy, gy, gz * gz));
    }
    if ((nm & 1) && tid == 0) {
        // pad odd tail so its min contribution is huge
        int p = nm >> 1;
        s_model[p * 8 + 1] = 0.f;
        s_model[p * 8 + 3] = 0.f;
        s_model[p * 8 + 5] = 0.f;
        s_model[p * 8 + 7] = FLT_MAX * 0.5f;
    }

    // ---- fused setup: thread 0 builds R = Rz@Ry@Rx, t, 1/scale ----
    if (tid == 0) {
        float ox = state[3], oy = state[4], oz = state[5];
        float sx = sinf(ox), cx = cosf(ox);
        float sy = sinf(oy), cy = cosf(oy);
        float sz = sinf(oz), cz = cosf(oz);
        s_par[0] = cz * cy;
        s_par[1] = cz * sy * sx - sz * cx;
        s_par[2] = cz * sy * cx + sz * sx;
        s_par[3] = sz * cy;
        s_par[4] = sz * sy * sx + cz * cx;
        s_par[5] = sz * sy * cx - cz * sx;
        s_par[6] = -sy;
        s_par[7] = cy * sx;
        s_par[8] = cy * cx;
        s_par[9]  = state[0];
        s_par[10] = state[1];
        s_par[11] = state[2];
        s_par[12] = 1.0f / scale[0];
    }
    __syncthreads();

    const int pid = tid & 127;          // point slot within CTA
    const int sub = tid >> 7;           // which quarter of the model set
    const int i = blockIdx.x * 128 + pid;
    const int ntot = nv + nt;
    const bool active = (i < ntot);

    float px = 0.f, py = 0.f, pz = 0.f, w = 0.f;
    if (active) {
        const float* src;
        int idx;
        if (i < nv) { src = vis; idx = i;      w = wv; }
        else        { src = tac; idx = i - nv; w = wt; }
        float vx = src[3 * idx + 0] - s_par[9];
        float vy = src[3 * idx + 1] - s_par[10];
        float vz = src[3 * idx + 2] - s_par[11];
        float inv_s = s_par[12];
        px = (vx * s_par[0] + vy * s_par[3] + vz * s_par[6]) * inv_s;
        py = (vx * s_par[1] + vy * s_par[4] + vz * s_par[7]) * inv_s;
        pz = (vx * s_par[2] + vy * s_par[5] + vz * s_par[8]) * inv_s;
    }

    const float a = fmaf(px, px, fmaf(py, py, pz * pz));
    const float qx = -2.0f * px, qy = -2.0f * py, qz = -2.0f * pz;

    // pack q into f32x2 duplicated halves
    uint64_t qx2, qy2, qz2;
    asm("mov.b64 %0, {%1,%1};" : "=l"(qx2) : "f"(qx));
    asm("mov.b64 %0, {%1,%1};" : "=l"(qy2) : "f"(qy));
    asm("mov.b64 %0, {%1,%1};" : "=l"(qz2) : "f"(qz));

    // this sub's slice of pairs
    const int pairs_per = (nm_pairs + 3) >> 2;
    int pb = sub * pairs_per; if (pb > nm_pairs) pb = nm_pairs;
    int pe = pb + pairs_per;  if (pe > nm_pairs) pe = nm_pairs;

    uint32_t addr;
    {
        uint64_t a64;
        asm("cvta.to.shared.u64 %0, %1;" : "=l"(a64) : "l"(s_model + (size_t)pb * 8));
        addr = (uint32_t)a64;
    }

    float m_lo = FLT_MAX, m_hi = FLT_MAX;
    #pragma unroll 4
    for (int p = pb; p < pe; ++p, addr += 32) {
        uint64_t x2, y2, z2, w2, d2;
        asm("ld.shared.v2.u64 {%0,%1}, [%2];"    : "=l"(x2), "=l"(y2) : "r"(addr));
        asm("ld.shared.v2.u64 {%0,%1}, [%2+16];" : "=l"(z2), "=l"(w2) : "r"(addr));
        asm("fma.rn.f32x2 %0, %1, %2, %3;" : "=l"(d2) : "l"(qz2), "l"(z2), "l"(w2));
        asm("fma.rn.f32x2 %0, %1, %2, %0;" : "+l"(d2) : "l"(qy2), "l"(y2));
        asm("fma.rn.f32x2 %0, %1, %2, %0;" : "+l"(d2) : "l"(qx2), "l"(x2));
        float dlo, dhi;
        asm("mov.b64 {%0,%1}, %2;" : "=f"(dlo), "=f"(dhi) : "l"(d2));
        m_lo = fminf(m_lo, dlo);
        m_hi = fminf(m_hi, dhi);
    }

    s_min[sub * 128 + pid] = fminf(m_lo, m_hi);
    __syncthreads();

    if (sub == 0) {
        float m = s_min[pid];
        m = fminf(m, s_min[128 + pid]);
        m = fminf(m, s_min[256 + pid]);
        m = fminf(m, s_min[384 + pid]);
        float val = active ? (a + m) * w : 0.0f;
        #pragma unroll
        for (int o = 16; o > 0; o >>= 1)
            val += __shfl_down_sync(0xffffffffu, val, o);
        if ((tid & 31) == 0) s_red[tid >> 5] = val;
    }
    __syncthreads();
    if (tid == 0)
        g_partials[blockIdx.x] = (s_red[0] + s_red[1]) + (s_red[2] + s_red[3]);
}

// Deterministic fixed-order final sum.
__global__ void final_kernel(float* __restrict__ out, int nb) {
    if (threadIdx.x == 0 && blockIdx.x == 0) {
        float s = 0.0f;
        for (int b = 0; b < nb; b++) s += g_partials[b];
        out[0] = s;
    }
}

extern "C" void kernel_launch(void* const* d_in, const int* in_sizes, int n_in,
                              void* d_out, int out_size) {
    const float* vis   = (const float*)d_in[0];  // visual_points  (16384,3)
    const float* tac   = (const float*)d_in[1];  // tactile_points (2048,3)
    const float* model = (const float*)d_in[2];  // model_points   (8192,3)
    const float* scale = (const float*)d_in[3];  // scalar
    const float* state = (const float*)d_in[4];  // (6,)
    float* out = (float*)d_out;

    int nv = in_sizes[0] / 3;
    int nt = in_sizes[1] / 3;
    int nm = in_sizes[2] / 3;

    int ntot = nv + nt;
    int nb = (ntot + 127) / 128;               // 144 for default shapes
    if (nb > NB_MAX) nb = NB_MAX;

    int nm_pairs = (nm + 1) / 2;
    size_t smem = (size_t)nm_pairs * 32;       // 131072 B for nm=8192
    cudaFuncSetAttribute(cd_kernel, cudaFuncAttributeMaxDynamicSharedMemorySize,
                         (int)smem);

    float wv = 1.0f / (float)nv;
    float wt = 0.1f / (float)nt;

    cd_kernel<<<nb, 512, smem>>>(vis, tac, model, scale, state,
                                 nv, nt, nm, wv, wt);
    final_kernel<<<1, 32>>>(out, nb);
}

// round 3
// speedup vs baseline: 2.0595x; 1.4605x over previous
#include <cuda_runtime.h>
#include <math.h>
#include <cstdint>
#include <float.h>

#define NB_MAX 256
__device__ float g_partials[NB_MAX];
__device__ unsigned int g_ticket;   // zero-init; last CTA resets it each launch

// 256 threads/CTA = 8 warps. Each CTA owns 128 pred points.
// Warp w covers model-pair slice w; lane holds P=4 pred points (idx k*32+lane).
// Model staged in SMEM pair-interleaved: [x0,x1,y0,y1,z0,z1,w0,w1] (w=|g|^2).
__global__ __launch_bounds__(256, 1)
void cd_kernel(const float* __restrict__ vis,
               const float* __restrict__ tac,
               const float* __restrict__ model,
               const float* __restrict__ scale,
               const float* __restrict__ state,
               float* __restrict__ out,
               int nv, int nt, int nm,
               float wv, float wt, int nb) {
    extern __shared__ float s_model[];        // nm_pairs * 8 floats
    __shared__ float s_par[13];
    __shared__ float s_min[8 * 128];
    __shared__ int s_last;

    const int tid  = threadIdx.x;
    const int lane = tid & 31;
    const int warp = tid >> 5;                // model slice id 0..7
    const int nm_pairs = (nm + 1) >> 1;

    // ---- stage model points (pair-interleaved, with |g|^2) ----
    for (int j = tid; j < nm; j += 256) {
        float gx = model[3 * j + 0];
        float gy = model[3 * j + 1];
        float gz = model[3 * j + 2];
        int p = j >> 1, o = j & 1;
        s_model[p * 8 + 0 + o] = gx;
        s_model[p * 8 + 2 + o] = gy;
        s_model[p * 8 + 4 + o] = gz;
        s_model[p * 8 + 6 + o] = fmaf(gx, gx, fmaf(gy, gy, gz * gz));
    }
    if ((nm & 1) && tid == 0) {
        int p = nm >> 1;
        s_model[p * 8 + 1] = 0.f; s_model[p * 8 + 3] = 0.f;
        s_model[p * 8 + 5] = 0.f; s_model[p * 8 + 7] = FLT_MAX * 0.5f;
    }

    // ---- fused setup: R = Rz@Ry@Rx, t, 1/scale ----
    if (tid == 0) {
        float ox = state[3], oy = state[4], oz = state[5];
        float sx = sinf(ox), cx = cosf(ox);
        float sy = sinf(oy), cy = cosf(oy);
        float sz = sinf(oz), cz = cosf(oz);
        s_par[0] = cz * cy;
        s_par[1] = cz * sy * sx - sz * cx;
        s_par[2] = cz * sy * cx + sz * sx;
        s_par[3] = sz * cy;
        s_par[4] = sz * sy * sx + cz * cx;
        s_par[5] = sz * sy * cx - cz * sx;
        s_par[6] = -sy;
        s_par[7] = cy * sx;
        s_par[8] = cy * cx;
        s_par[9]  = state[0];
        s_par[10] = state[1];
        s_par[11] = state[2];
        s_par[12] = 1.0f / scale[0];
    }
    __syncthreads();

    const int ntot = nv + nt;

    // ---- per-thread transform of P=4 pred points ----
    float a[4], wgt[4];
    uint64_t qx2[4], qy2[4], qz2[4];
    #pragma unroll
    for (int k = 0; k < 4; k++) {
        int pidx = k * 32 + lane;                 // point slot in CTA
        int i = blockIdx.x * 128 + pidx;
        float px = 0.f, py = 0.f, pz = 0.f;
        wgt[k] = 0.f;
        if (i < ntot) {
            const float* src; int idx;
            if (i < nv) { src = vis; idx = i;      wgt[k] = wv; }
            else        { src = tac; idx = i - nv; wgt[k] = wt; }
            float vx = src[3 * idx + 0] - s_par[9];
            float vy = src[3 * idx + 1] - s_par[10];
            float vz = src[3 * idx + 2] - s_par[11];
            float inv_s = s_par[12];
            px = (vx * s_par[0] + vy * s_par[3] + vz * s_par[6]) * inv_s;
            py = (vx * s_par[1] + vy * s_par[4] + vz * s_par[7]) * inv_s;
            pz = (vx * s_par[2] + vy * s_par[5] + vz * s_par[8]) * inv_s;
        }
        a[k] = fmaf(px, px, fmaf(py, py, pz * pz));
        float qx = -2.0f * px, qy = -2.0f * py, qz = -2.0f * pz;
        asm("mov.b64 %0, {%1,%1};" : "=l"(qx2[k]) : "f"(qx));
        asm("mov.b64 %0, {%1,%1};" : "=l"(qy2[k]) : "f"(qy));
        asm("mov.b64 %0, {%1,%1};" : "=l"(qz2[k]) : "f"(qz));
    }

    // ---- this warp's slice of model pairs ----
    const int pairs_per = (nm_pairs + 7) >> 3;
    int pb = warp * pairs_per; if (pb > nm_pairs) pb = nm_pairs;
    int pe = pb + pairs_per;   if (pe > nm_pairs) pe = nm_pairs;

    uint32_t addr;
    {
        uint64_t a64;
        asm("cvta.to.shared.u64 %0, %1;" : "=l"(a64) : "l"(s_model + (size_t)pb * 8));
        addr = (uint32_t)a64;
    }

    float m_lo[4], m_hi[4];
    #pragma unroll
    for (int k = 0; k < 4; k++) { m_lo[k] = FLT_MAX; m_hi[k] = FLT_MAX; }

    #pragma unroll 4
    for (int p = pb; p < pe; ++p, addr += 32) {
        uint64_t x2, y2, z2, w2;
        asm("ld.shared.v2.u64 {%0,%1}, [%2];"    : "=l"(x2), "=l"(y2) : "r"(addr));
        asm("ld.shared.v2.u64 {%0,%1}, [%2+16];" : "=l"(z2), "=l"(w2) : "r"(addr));
        #pragma unroll
        for (int k = 0; k < 4; k++) {
            uint64_t d2;
            asm("fma.rn.f32x2 %0, %1, %2, %3;" : "=l"(d2) : "l"(qz2[k]), "l"(z2), "l"(w2));
            asm("fma.rn.f32x2 %0, %1, %2, %0;" : "+l"(d2) : "l"(qy2[k]), "l"(y2));
            asm("fma.rn.f32x2 %0, %1, %2, %0;" : "+l"(d2) : "l"(qx2[k]), "l"(x2));
            float dlo, dhi;
            asm("mov.b64 {%0,%1}, %2;" : "=f"(dlo), "=f"(dhi) : "l"(d2));
            m_lo[k] = fminf(m_lo[k], dlo);
            m_hi[k] = fminf(m_hi[k], dhi);
        }
    }

    #pragma unroll
    for (int k = 0; k < 4; k++)
        s_min[warp * 128 + k * 32 + lane] = fminf(m_lo[k], m_hi[k]);
    __syncthreads();

    // ---- per-CTA reduction (warp 0) ----
    if (warp == 0) {
        float vsum = 0.0f;
        #pragma unroll
        for (int k = 0; k < 4; k++) {
            int pidx = k * 32 + lane;
            float m = s_min[pidx];
            #pragma unroll
            for (int s = 1; s < 8; s++)
                m = fminf(m, s_min[s * 128 + pidx]);
            int i = blockIdx.x * 128 + pidx;
            if (i < ntot) vsum += (a[k] + m) * wgt[k];
        }
        #pragma unroll
        for (int o = 16; o > 0; o >>= 1)
            vsum += __shfl_down_sync(0xffffffffu, vsum, o);
        if (lane == 0) g_partials[blockIdx.x] = vsum;
    }
    __syncthreads();

    // ---- last-CTA-done fused final reduction ----
    if (tid == 0) {
        __threadfence();
        unsigned int t = atomicAdd(&g_ticket, 1u);
        s_last = (t == (unsigned int)(nb - 1)) ? 1 : 0;
    }
    __syncthreads();
    if (s_last && warp == 0) {
        // fixed lane-strided partition + fixed shuffle tree -> deterministic
        float s = 0.0f;
        for (int b = lane; b < nb; b += 32)
            s += *((volatile float*)&g_partials[b]);
        #pragma unroll
        for (int o = 16; o > 0; o >>= 1)
            s += __shfl_down_sync(0xffffffffu, s, o);
        if (lane == 0) {
            out[0] = s;
            g_ticket = 0;   // reset for next graph replay
        }
    }
}

extern "C" void kernel_launch(void* const* d_in, const int* in_sizes, int n_in,
                              void* d_out, int out_size) {
    const float* vis   = (const float*)d_in[0];  // visual_points  (16384,3)
    const float* tac   = (const float*)d_in[1];  // tactile_points (2048,3)
    const float* model = (const float*)d_in[2];  // model_points   (8192,3)
    const float* scale = (const float*)d_in[3];  // scalar
    const float* state = (const float*)d_in[4];  // (6,)
    float* out = (float*)d_out;

    int nv = in_sizes[0] / 3;
    int nt = in_sizes[1] / 3;
    int nm = in_sizes[2] / 3;

    int ntot = nv + nt;
    int nb = (ntot + 127) / 128;               // 144 for default shapes
    if (nb > NB_MAX) nb = NB_MAX;

    int nm_pairs = (nm + 1) / 2;
    size_t smem = (size_t)nm_pairs * 32;       // 131072 B for nm=8192
    cudaFuncSetAttribute(cd_kernel, cudaFuncAttributeMaxDynamicSharedMemorySize,
                         (int)smem);

    float wv = 1.0f / (float)nv;
    float wt = 0.1f / (float)nt;

    cd_kernel<<<nb, 256, smem>>>(vis, tac, model, scale, state, out,
                                 nv, nt, nm, wv, wt, nb);
}